// round 5
// baseline (speedup 1.0000x reference)
#include <cuda_runtime.h>
#include <cstdint>

// ---------------------------------------------------------------------------
// DispatchByVariable: grouped GEMM, token -> expert by bucketizing x[...,0]
//   x  : [8, 4096, 512] f32   (32768 tokens x 512)
//   W  : [8, 512, 512]  f32   (8 experts)
//   out: [8, 4096, 512] f32
// bin(t) = sum_b (x[t,0] > BINS[b]),  BINS = {-1.5,-1,-0.5,0,0.5,1,1.5}
// out[t] = x[t] @ W[bin(t)]
// ---------------------------------------------------------------------------

#define NTOK   32768
#define DIM    512
#define NBIN   8
#define BM     128
#define BN     128
#define BK     16
#define PERM_CAP (NTOK + NBIN * BM)          // 33792
#define MAX_TILES_M (NTOK / BM + NBIN)       // 264

// ------------------------- device scratch (no allocs) ----------------------
__device__ int g_binof[NTOK];
__device__ int g_perm[PERM_CAP];
__device__ int g_counts[NBIN];
__device__ int g_cursor[NBIN];
__device__ int g_offsets[NBIN + 1];

// ------------------------- packed f32x2 helpers ----------------------------
__device__ __forceinline__ unsigned long long pack2(float lo, float hi) {
    unsigned long long r;
    asm("mov.b64 %0, {%1, %2};" : "=l"(r) : "f"(lo), "f"(hi));
    return r;
}
__device__ __forceinline__ void unpack2(unsigned long long v, float& lo, float& hi) {
    asm("mov.b64 {%0, %1}, %2;" : "=f"(lo), "=f"(hi) : "l"(v));
}
#define FMA2(acc, a, b) \
    asm("fma.rn.f32x2 %0, %1, %2, %0;" : "+l"(acc) : "l"(a), "l"(b))

// ------------------------- prep kernels ------------------------------------
__global__ void k_init() {
    int i = blockIdx.x * blockDim.x + threadIdx.x;
    if (i < PERM_CAP) g_perm[i] = -1;
    if (i < NBIN) { g_counts[i] = 0; g_cursor[i] = 0; }
}

__global__ void k_bucketize(const float* __restrict__ x) {
    int t = blockIdx.x * blockDim.x + threadIdx.x;
    if (t >= NTOK) return;
    float y = x[(size_t)t * DIM];
    int b = 0;
    b += (y > -1.5f); b += (y > -1.0f); b += (y > -0.5f); b += (y > 0.0f);
    b += (y >  0.5f); b += (y >  1.0f); b += (y >  1.5f);
    g_binof[t] = b;
    atomicAdd(&g_counts[b], 1);
}

__global__ void k_offsets() {
    // single thread: padded (to BM) exclusive prefix sum of bin counts
    int off = 0;
    g_offsets[0] = 0;
#pragma unroll
    for (int k = 0; k < NBIN; k++) {
        int padded = ((g_counts[k] + BM - 1) / BM) * BM;
        off += padded;
        g_offsets[k + 1] = off;
    }
}

__global__ void k_scatter() {
    int t = blockIdx.x * blockDim.x + threadIdx.x;
    if (t >= NTOK) return;
    int b = g_binof[t];
    int p = atomicAdd(&g_cursor[b], 1);
    g_perm[g_offsets[b] + p] = t;
}

// ------------------------- grouped SGEMM -----------------------------------
// tile: BM x BN x BK, 256 threads, each thread 8x8 outputs (4+4 split @ stride 64)
__global__ __launch_bounds__(256, 2)
void k_gemm(const float* __restrict__ x, const float* __restrict__ W,
            float* __restrict__ out) {
    __shared__ float As[BK][BM];       // A transposed: As[k][row]
    __shared__ float Bs[BK][BN];
    __shared__ int   rowid[BM];

    const int total = g_offsets[NBIN];
    const int row0  = blockIdx.x * BM;
    if (row0 >= total) return;

    int bin = 0;
#pragma unroll
    for (int k = 1; k < NBIN; k++)
        if (row0 >= g_offsets[k]) bin = k;
    const float* __restrict__ Wk = W + (size_t)bin * DIM * DIM;

    const int tid = threadIdx.x;
    if (tid < BM) rowid[tid] = g_perm[row0 + tid];
    __syncthreads();

    const int n0 = blockIdx.y * BN;
    const int ty = tid >> 4;            // 0..15
    const int tx = tid & 15;            // 0..15

    unsigned long long acc[8][4];       // 8 rows x 8 cols as 4 f32x2 pairs
#pragma unroll
    for (int i = 0; i < 8; i++)
#pragma unroll
        for (int j = 0; j < 4; j++) acc[i][j] = 0ull;

    for (int kt = 0; kt < DIM; kt += BK) {
        // --- load A tile (gathered rows), store transposed ---
#pragma unroll
        for (int i = 0; i < 2; i++) {
            int s  = tid + i * 256;        // 0..511
            int c4 = s >> 7;               // 0..3 (float4 column group)
            int r  = s & 127;              // row within tile
            int tok = rowid[r];
            float4 v = make_float4(0.f, 0.f, 0.f, 0.f);
            if (tok >= 0)
                v = *(const float4*)(x + (size_t)tok * DIM + kt + c4 * 4);
            As[c4 * 4 + 0][r] = v.x;
            As[c4 * 4 + 1][r] = v.y;
            As[c4 * 4 + 2][r] = v.z;
            As[c4 * 4 + 3][r] = v.w;
        }
        // --- load B tile (coalesced) ---
#pragma unroll
        for (int i = 0; i < 2; i++) {
            int s = tid + i * 256;         // 0..511
            int d = s >> 5;                // 0..15
            int n = (s & 31) * 4;          // 0..124
            float4 v = *(const float4*)(Wk + (size_t)(kt + d) * DIM + n0 + n);
            *(float4*)&Bs[d][n] = v;
        }
        __syncthreads();

#pragma unroll
        for (int kk = 0; kk < BK; kk++) {
            float4 a0 = *(const float4*)&As[kk][ty * 4];
            float4 a1 = *(const float4*)&As[kk][64 + ty * 4];
            float4 b0 = *(const float4*)&Bs[kk][tx * 4];
            float4 b1 = *(const float4*)&Bs[kk][64 + tx * 4];

            unsigned long long bb[4];
            bb[0] = pack2(b0.x, b0.y); bb[1] = pack2(b0.z, b0.w);
            bb[2] = pack2(b1.x, b1.y); bb[3] = pack2(b1.z, b1.w);

            float av[8] = {a0.x, a0.y, a0.z, a0.w, a1.x, a1.y, a1.z, a1.w};
#pragma unroll
            for (int i = 0; i < 8; i++) {
                unsigned long long ad = pack2(av[i], av[i]);
                FMA2(acc[i][0], ad, bb[0]);
                FMA2(acc[i][1], ad, bb[1]);
                FMA2(acc[i][2], ad, bb[2]);
                FMA2(acc[i][3], ad, bb[3]);
            }
        }
        __syncthreads();
    }

    // --- epilogue: scatter rows back to their token positions ---
#pragma unroll
    for (int i = 0; i < 8; i++) {
        int r = (i < 4) ? (ty * 4 + i) : (64 + ty * 4 + (i - 4));
        int tok = rowid[r];
        if (tok < 0) continue;
        float o[8];
        unpack2(acc[i][0], o[0], o[1]);
        unpack2(acc[i][1], o[2], o[3]);
        unpack2(acc[i][2], o[4], o[5]);
        unpack2(acc[i][3], o[6], o[7]);
        float* dst = out + (size_t)tok * DIM + n0;
        *(float4*)(dst + tx * 4)      = make_float4(o[0], o[1], o[2], o[3]);
        *(float4*)(dst + 64 + tx * 4) = make_float4(o[4], o[5], o[6], o[7]);
    }
}

// ------------------------- launch ------------------------------------------
extern "C" void kernel_launch(void* const* d_in, const int* in_sizes, int n_in,
                              void* d_out, int out_size) {
    const float* x = (const float*)d_in[0];   // [8,4096,512] f32
    const float* W = (const float*)d_in[1];   // [8,512,512]  f32
    float* out = (float*)d_out;

    k_init<<<(PERM_CAP + 255) / 256, 256>>>();
    k_bucketize<<<(NTOK + 255) / 256, 256>>>(x);
    k_offsets<<<1, 1>>>();
    k_scatter<<<(NTOK + 255) / 256, 256>>>();

    dim3 grid(MAX_TILES_M, BN == 128 ? DIM / BN : 4);
    k_gemm<<<grid, 256>>>(x, W, out);
}

// round 7
// speedup vs baseline: 1.6917x; 1.6917x over previous
#include <cuda_runtime.h>
#include <cuda_bf16.h>
#include <cstdint>

// ---------------------------------------------------------------------------
// DispatchByVariable: grouped GEMM via mma.sync bf16 split (hi/lo, 3 MMAs)
//   x  : [8,4096,512] f32  (32768 tokens x 512)
//   W  : [8,512,512]  f32  (8 experts)
//   out[t] = x[t] @ W[bin(t)],  bin = sum(x[t,0] > {-1.5..1.5})
// tcgen05 is unavailable (harness compiles for plain sm_100), so use
// warp-level HMMA (mma.sync m16n8k16 bf16) with a 3-stage cp.async pipeline.
// ---------------------------------------------------------------------------

#define NTOK 32768
#define DIM  512
#define NBIN 8
#define BM   128
#define BN   128
#define BKC  32
#define NCHUNK (DIM / BKC)                 // 16
#define PERM_CAP (NTOK + NBIN * BM)        // 33792
#define MAX_TILES_M (NTOK / BM + NBIN)     // 264
#define NSTAGE 3

// ---------------- device scratch (no allocs) --------------------------------
__device__ int g_binof[NTOK];
__device__ int g_perm[PERM_CAP];
__device__ int g_counts[NBIN];
__device__ int g_cursor[NBIN];
__device__ int g_offsets[NBIN + 1];
__device__ __align__(256) __nv_bfloat16 g_xhi[NTOK * DIM];       // 32 MB
__device__ __align__(256) __nv_bfloat16 g_xlo[NTOK * DIM];       // 32 MB
__device__ __align__(256) __nv_bfloat16 g_whi[NBIN * DIM * DIM]; // 4 MB, K-major [e][n][k]
__device__ __align__(256) __nv_bfloat16 g_wlo[NBIN * DIM * DIM];

// ---------------- smem layout (dynamic) --------------------------------------
// per stage: A = 128 rows x 128B (hi 64B | lo 64B), B same -> 32 KB/stage
#define SM_ROWID 0            // 128 ints
#define SM_TILES 1024
#define STAGE_BYTES 32768
#define SM_TOTAL (SM_TILES + NSTAGE * STAGE_BYTES)   // 99328

// ---------------- PTX helpers ------------------------------------------------
__device__ __forceinline__ uint32_t smem_u32(const void* p) {
    uint32_t a;
    asm("{ .reg .u64 t; cvta.to.shared.u64 t, %1; cvt.u32.u64 %0, t; }"
        : "=r"(a) : "l"(p));
    return a;
}
__device__ __forceinline__ uint32_t sw128(uint32_t b) { return b ^ ((b >> 3) & 0x70); }

__device__ __forceinline__ void cp16(uint32_t d, const void* s) {
    asm volatile("cp.async.cg.shared.global [%0], [%1], 16;" :: "r"(d), "l"(s));
}
__device__ __forceinline__ void cp_commit() { asm volatile("cp.async.commit_group;"); }
__device__ __forceinline__ void cp_wait1()  { asm volatile("cp.async.wait_group 1;"); }
__device__ __forceinline__ void cp_wait0()  { asm volatile("cp.async.wait_group 0;"); }

__device__ __forceinline__ void ldsm4(uint32_t* r, uint32_t a) {
    asm volatile("ldmatrix.sync.aligned.m8n8.x4.shared.b16 {%0,%1,%2,%3}, [%4];"
                 : "=r"(r[0]), "=r"(r[1]), "=r"(r[2]), "=r"(r[3]) : "r"(a));
}
__device__ __forceinline__ void mma16816(float* c, const uint32_t* a,
                                         const uint32_t* b0) {
    asm volatile(
        "mma.sync.aligned.m16n8k16.row.col.f32.bf16.bf16.f32 "
        "{%0,%1,%2,%3},{%4,%5,%6,%7},{%8,%9},{%0,%1,%2,%3};"
        : "+f"(c[0]), "+f"(c[1]), "+f"(c[2]), "+f"(c[3])
        : "r"(a[0]), "r"(a[1]), "r"(a[2]), "r"(a[3]), "r"(b0[0]), "r"(b0[1]));
}

// ---------------- prep kernels ------------------------------------------------
__global__ void k_init() {
    int i = blockIdx.x * blockDim.x + threadIdx.x;
    if (i < PERM_CAP) g_perm[i] = -1;
    if (i < NBIN) { g_counts[i] = 0; g_cursor[i] = 0; }
}

__global__ void k_bucketize(const float* __restrict__ x) {
    int t = blockIdx.x * blockDim.x + threadIdx.x;
    if (t >= NTOK) return;
    float y = x[(size_t)t * DIM];
    int b = 0;
    b += (y > -1.5f); b += (y > -1.0f); b += (y > -0.5f); b += (y > 0.0f);
    b += (y >  0.5f); b += (y >  1.0f); b += (y >  1.5f);
    g_binof[t] = b;
    atomicAdd(&g_counts[b], 1);
}

__global__ void k_offsets() {
    int off = 0;
    g_offsets[0] = 0;
#pragma unroll
    for (int k = 0; k < NBIN; k++) {
        off += ((g_counts[k] + BM - 1) / BM) * BM;
        g_offsets[k + 1] = off;
    }
}

__global__ void k_scatter() {
    int t = blockIdx.x * blockDim.x + threadIdx.x;
    if (t >= NTOK) return;
    int b = g_binof[t];
    int p = atomicAdd(&g_cursor[b], 1);
    g_perm[g_offsets[b] + p] = t;
}

// convert x -> bf16 hi/lo (vectorized by float4)
__global__ void k_convert_x(const float* __restrict__ x) {
    int i = blockIdx.x * blockDim.x + threadIdx.x;   // float4 index
    float4 v = ((const float4*)x)[i];
    __nv_bfloat16 h0 = __float2bfloat16(v.x), h1 = __float2bfloat16(v.y);
    __nv_bfloat16 h2 = __float2bfloat16(v.z), h3 = __float2bfloat16(v.w);
    __nv_bfloat16 l0 = __float2bfloat16(v.x - __bfloat162float(h0));
    __nv_bfloat16 l1 = __float2bfloat16(v.y - __bfloat162float(h1));
    __nv_bfloat16 l2 = __float2bfloat16(v.z - __bfloat162float(h2));
    __nv_bfloat16 l3 = __float2bfloat16(v.w - __bfloat162float(h3));
    __nv_bfloat162 p;
    p.x = h0; p.y = h1; ((__nv_bfloat162*)g_xhi)[2 * i]     = p;
    p.x = h2; p.y = h3; ((__nv_bfloat162*)g_xhi)[2 * i + 1] = p;
    p.x = l0; p.y = l1; ((__nv_bfloat162*)g_xlo)[2 * i]     = p;
    p.x = l2; p.y = l3; ((__nv_bfloat162*)g_xlo)[2 * i + 1] = p;
}

// transpose W [e][k][n] -> Wt [e][n][k], convert to bf16 hi/lo
__global__ void k_convert_w(const float* __restrict__ W) {
    __shared__ float t[32][33];
    int e = blockIdx.z;
    int k0 = blockIdx.x * 32, nb = blockIdx.y * 32;
    int tx = threadIdx.x, ty = threadIdx.y;   // 32 x 8
    const float* Wb = W + (size_t)e * DIM * DIM;
#pragma unroll
    for (int i = 0; i < 4; i++)
        t[ty + i * 8][tx] = Wb[(size_t)(k0 + ty + i * 8) * DIM + nb + tx];
    __syncthreads();
#pragma unroll
    for (int i = 0; i < 4; i++) {
        float v = t[tx][ty + i * 8];  // = W[e][k0+tx][nb+ty+i*8]
        __nv_bfloat16 h = __float2bfloat16(v);
        __nv_bfloat16 l = __float2bfloat16(v - __bfloat162float(h));
        size_t o = (size_t)e * DIM * DIM + (size_t)(nb + ty + i * 8) * DIM + (k0 + tx);
        g_whi[o] = h;
        g_wlo[o] = l;
    }
}

// ---------------- HMMA grouped GEMM -------------------------------------------
__global__ __launch_bounds__(256, 1)
void k_gemm(float* __restrict__ out) {
    extern __shared__ char smem[];
    const int tid = threadIdx.x;
    const int total = g_offsets[NBIN];
    const int row0 = blockIdx.x * BM;
    if (row0 >= total) return;

    const uint32_t sb = smem_u32(smem);
    int* rowid_s = (int*)(smem + SM_ROWID);

    int bin = 0;
#pragma unroll
    for (int k = 1; k < NBIN; k++)
        if (row0 >= g_offsets[k]) bin = k;

    if (tid < BM) rowid_s[tid] = g_perm[row0 + tid];
    __syncthreads();

    // gather tokens for A loads: thread covers rows (tid>>3) + 32*i
    int tokA[4];
#pragma unroll
    for (int i = 0; i < 4; i++) {
        int t = rowid_s[(tid >> 3) + i * 32];
        tokA[i] = t < 0 ? 0 : t;
    }

    const int n0 = blockIdx.y * BN;
    const size_t wrow0 = (size_t)bin * DIM + n0;   // W n-row base

    auto load_chunk = [&](int ch) {
        const int st = ch % NSTAGE;
        const int kt = ch * BKC;
        const uint32_t ab = sb + SM_TILES + st * STAGE_BYTES;
        const uint32_t bb = ab + 16384;
#pragma unroll
        for (int i = 0; i < 4; i++) {
            int s = tid + i * 256;
            int r = s >> 3, c = s & 7;                       // c: 16B chunk in 128B row
            const __nv_bfloat16* src = (c < 4)
                ? g_xhi + ((size_t)tokA[i] * DIM + kt + c * 8)
                : g_xlo + ((size_t)tokA[i] * DIM + kt + (c - 4) * 8);
            cp16(ab + sw128((uint32_t)(r * 128 + c * 16)), src);
        }
#pragma unroll
        for (int i = 0; i < 4; i++) {
            int s = tid + i * 256;
            int r = s >> 3, c = s & 7;
            const __nv_bfloat16* src = (c < 4)
                ? g_whi + ((wrow0 + r) * DIM + kt + c * 8)
                : g_wlo + ((wrow0 + r) * DIM + kt + (c - 4) * 8);
            cp16(bb + sw128((uint32_t)(r * 128 + c * 16)), src);
        }
        cp_commit();
    };

    load_chunk(0);
    load_chunk(1);

    const int lane = tid & 31;
    const int wid = tid >> 5;
    const int wm = (wid & 1) * 64;       // warp M offset (2 warps in M)
    const int wn = (wid >> 1) * 32;      // warp N offset (4 warps in N)
    const int lrow = lane & 15;          // ldmatrix row within 16-row tile
    const int lc16 = (lane >> 4) * 16;   // ldmatrix 16B col select

    float acc[4][4][4];
#pragma unroll
    for (int i = 0; i < 4; i++)
#pragma unroll
        for (int j = 0; j < 4; j++)
#pragma unroll
            for (int q = 0; q < 4; q++) acc[i][j][q] = 0.f;

#pragma unroll 1
    for (int c = 0; c < NCHUNK; c++) {
        if (c + 1 < NCHUNK) cp_wait1(); else cp_wait0();
        __syncthreads();
        if (c + 2 < NCHUNK) load_chunk(c + 2);

        const uint32_t ab = sb + SM_TILES + (c % NSTAGE) * STAGE_BYTES;
        const uint32_t bb = ab + 16384;

#pragma unroll
        for (int kk = 0; kk < 2; kk++) {        // two k16 steps per 32-chunk
            uint32_t Ah[4][4], Al[4][4];
#pragma unroll
            for (int mt = 0; mt < 4; mt++) {
                uint32_t off = (uint32_t)((wm + mt * 16 + lrow) * 128 + kk * 32 + lc16);
                ldsm4(Ah[mt], ab + sw128(off));
                ldsm4(Al[mt], ab + sw128(off + 64));
            }
            uint32_t Bh[4][2], Bl[4][2];
#pragma unroll
            for (int bt = 0; bt < 2; bt++) {    // x4 covers two n8 tiles
                uint32_t off = (uint32_t)((wn + bt * 16 + lrow) * 128 + kk * 32 + lc16);
                uint32_t r[4];
                ldsm4(r, bb + sw128(off));
                Bh[2 * bt][0] = r[0]; Bh[2 * bt][1] = r[2];
                Bh[2 * bt + 1][0] = r[1]; Bh[2 * bt + 1][1] = r[3];
                ldsm4(r, bb + sw128(off + 64));
                Bl[2 * bt][0] = r[0]; Bl[2 * bt][1] = r[2];
                Bl[2 * bt + 1][0] = r[1]; Bl[2 * bt + 1][1] = r[3];
            }
#pragma unroll
            for (int mt = 0; mt < 4; mt++)
#pragma unroll
                for (int nt = 0; nt < 4; nt++) {
                    mma16816(acc[mt][nt], Ah[mt], Bh[nt]);
                    mma16816(acc[mt][nt], Ah[mt], Bl[nt]);
                    mma16816(acc[mt][nt], Al[mt], Bh[nt]);
                }
        }
        __syncthreads();
    }

    // epilogue: scatter acc to gmem through perm
    const int rq = lane >> 2;          // 0..7
    const int cq = (lane & 3) * 2;
#pragma unroll
    for (int mt = 0; mt < 4; mt++) {
        int rA = wm + mt * 16 + rq;
        int tA = rowid_s[rA];
        int tB = rowid_s[rA + 8];
#pragma unroll
        for (int nt = 0; nt < 4; nt++) {
            int col = n0 + wn + nt * 8 + cq;
            if (tA >= 0)
                *(float2*)(out + (size_t)tA * DIM + col) =
                    make_float2(acc[mt][nt][0], acc[mt][nt][1]);
            if (tB >= 0)
                *(float2*)(out + (size_t)tB * DIM + col) =
                    make_float2(acc[mt][nt][2], acc[mt][nt][3]);
        }
    }
}

// ---------------- launch --------------------------------------------------------
extern "C" void kernel_launch(void* const* d_in, const int* in_sizes, int n_in,
                              void* d_out, int out_size) {
    const float* x = (const float*)d_in[0];   // [8,4096,512] f32
    const float* W = (const float*)d_in[1];   // [8,512,512]  f32
    float* out = (float*)d_out;

    k_init<<<(PERM_CAP + 255) / 256, 256>>>();
    k_bucketize<<<(NTOK + 255) / 256, 256>>>(x);
    k_offsets<<<1, 1>>>();
    k_scatter<<<(NTOK + 255) / 256, 256>>>();
    k_convert_x<<<(NTOK * DIM / 4) / 256, 256>>>(x);
    k_convert_w<<<dim3(DIM / 32, DIM / 32, NBIN), dim3(32, 8)>>>(W);

    cudaFuncSetAttribute(k_gemm, cudaFuncAttributeMaxDynamicSharedMemorySize, SM_TOTAL);
    k_gemm<<<dim3(MAX_TILES_M, DIM / BN), 256, SM_TOTAL>>>(out);
}

// round 8
// speedup vs baseline: 1.9208x; 1.1354x over previous
#include <cuda_runtime.h>
#include <cuda_bf16.h>
#include <cstdint>

// ---------------------------------------------------------------------------
// DispatchByVariable: grouped GEMM via mma.sync bf16 split (hi/lo, 3 MMAs)
//   x  : [8,4096,512] f32  (32768 tokens x 512)
//   W  : [8,512,512]  f32  (8 experts)
//   out[t] = x[t] @ W[bin(t)],  bin = sum(x[t,0] > {-1.5..1.5})
// R7 post-mortem: GEMM latency-exposed at 1 CTA/SM; prep atomics serialized.
// R8: histogram prep (no global atomics), fused converts, occupancy-2 GEMM.
// ---------------------------------------------------------------------------

#define NTOK 32768
#define DIM  512
#define NBIN 8
#define BM   128
#define BN   128
#define BKC  32
#define NCHUNK (DIM / BKC)                 // 16
#define PERM_CAP (NTOK + NBIN * BM)        // 33792
#define MAX_TILES_M (NTOK / BM + NBIN)     // 264
#define NSTAGE 3
#define NTBLK (NTOK / 256)                 // 128 token blocks

// ---------------- device scratch (no allocs) --------------------------------
__device__ int g_binof[NTOK];
__device__ int g_perm[PERM_CAP];
__device__ int g_hist[NTBLK][NBIN];
__device__ int g_offsets[NBIN + 1];
__device__ __align__(256) __nv_bfloat16 g_xhi[NTOK * DIM];       // 32 MB
__device__ __align__(256) __nv_bfloat16 g_xlo[NTOK * DIM];       // 32 MB
__device__ __align__(256) __nv_bfloat16 g_whi[NBIN * DIM * DIM]; // 4 MB, K-major [e][n][k]
__device__ __align__(256) __nv_bfloat16 g_wlo[NBIN * DIM * DIM];

// ---------------- smem layout for GEMM (dynamic) -----------------------------
#define SM_ROWID 0            // 128 ints
#define SM_TILES 1024
#define STAGE_BYTES 32768     // A 16KB + B 16KB
#define SM_TOTAL (SM_TILES + NSTAGE * STAGE_BYTES)   // 99328 -> 2 CTAs/SM fits

// ---------------- PTX helpers ------------------------------------------------
__device__ __forceinline__ uint32_t smem_u32(const void* p) {
    uint32_t a;
    asm("{ .reg .u64 t; cvta.to.shared.u64 t, %1; cvt.u32.u64 %0, t; }"
        : "=r"(a) : "l"(p));
    return a;
}
__device__ __forceinline__ uint32_t sw128(uint32_t b) { return b ^ ((b >> 3) & 0x70); }

__device__ __forceinline__ void cp16(uint32_t d, const void* s) {
    asm volatile("cp.async.cg.shared.global [%0], [%1], 16;" :: "r"(d), "l"(s));
}
__device__ __forceinline__ void cp_commit() { asm volatile("cp.async.commit_group;"); }
__device__ __forceinline__ void cp_wait1()  { asm volatile("cp.async.wait_group 1;"); }
__device__ __forceinline__ void cp_wait0()  { asm volatile("cp.async.wait_group 0;"); }

__device__ __forceinline__ void ldsm4(uint32_t* r, uint32_t a) {
    asm volatile("ldmatrix.sync.aligned.m8n8.x4.shared.b16 {%0,%1,%2,%3}, [%4];"
                 : "=r"(r[0]), "=r"(r[1]), "=r"(r[2]), "=r"(r[3]) : "r"(a));
}
__device__ __forceinline__ void mma16816(float* c, const uint32_t* a,
                                         const uint32_t* b0) {
    asm volatile(
        "mma.sync.aligned.m16n8k16.row.col.f32.bf16.bf16.f32 "
        "{%0,%1,%2,%3},{%4,%5,%6,%7},{%8,%9},{%0,%1,%2,%3};"
        : "+f"(c[0]), "+f"(c[1]), "+f"(c[2]), "+f"(c[3])
        : "r"(a[0]), "r"(a[1]), "r"(a[2]), "r"(a[3]), "r"(b0[0]), "r"(b0[1]));
}

// ---------------- prep kernel 1: perm init + bucketize (smem hist) -----------
__global__ void k_prep(const float* __restrict__ x) {
    __shared__ int hist[NBIN];
    const int b = blockIdx.x, tid = threadIdx.x;
    const int i = b * 256 + tid;
    if (i < PERM_CAP) g_perm[i] = -1;
    if (b < NTBLK) {
        if (tid < NBIN) hist[tid] = 0;
        __syncthreads();
        float y = x[(size_t)i * DIM];
        int bin = 0;
        bin += (y > -1.5f); bin += (y > -1.0f); bin += (y > -0.5f); bin += (y > 0.0f);
        bin += (y >  0.5f); bin += (y >  1.0f); bin += (y >  1.5f);
        g_binof[i] = bin;
        atomicAdd(&hist[bin], 1);          // smem only
        __syncthreads();
        if (tid < NBIN) g_hist[b][tid] = hist[tid];
    }
}

// ---------------- prep kernel 2: deterministic scatter (no global atomics) ---
__global__ void k_scatter() {
    __shared__ int base[NBIN], totals[NBIN], offs[NBIN], cnt[NBIN];
    const int b = blockIdx.x, tid = threadIdx.x;
    if (tid < NBIN) {
        int pre = 0, tot = 0;
        for (int q = 0; q < NTBLK; q++) {
            int h = g_hist[q][tid];
            if (q < b) pre += h;
            tot += h;
        }
        base[tid] = pre; totals[tid] = tot; cnt[tid] = 0;
    }
    __syncthreads();
    if (tid == 0) {
        int off = 0;
        for (int k = 0; k < NBIN; k++) {
            offs[k] = off;
            if (b == 0) g_offsets[k] = off;
            off += ((totals[k] + BM - 1) / BM) * BM;
        }
        if (b == 0) g_offsets[NBIN] = off;
    }
    __syncthreads();
    const int t = b * 256 + tid;
    const int bin = g_binof[t];
    const int r = atomicAdd(&cnt[bin], 1);     // smem only
    g_perm[offs[bin] + base[bin] + r] = t;
}

// ---------------- fused convert: x -> hi/lo bf16, W -> transposed hi/lo ------
#define NXB (NTOK * DIM / 4 / 256)    // 16384 blocks for x
#define NWB (16 * 16 * NBIN)          // 2048 blocks for W
__global__ void k_convert(const float* __restrict__ x, const float* __restrict__ W) {
    __shared__ float t[32][33];
    const int b = blockIdx.x, tid = threadIdx.x;
    if (b < NXB) {
        int i = b * 256 + tid;                 // float4 index
        float4 v = ((const float4*)x)[i];
        __nv_bfloat16 h0 = __float2bfloat16(v.x), h1 = __float2bfloat16(v.y);
        __nv_bfloat16 h2 = __float2bfloat16(v.z), h3 = __float2bfloat16(v.w);
        __nv_bfloat16 l0 = __float2bfloat16(v.x - __bfloat162float(h0));
        __nv_bfloat16 l1 = __float2bfloat16(v.y - __bfloat162float(h1));
        __nv_bfloat16 l2 = __float2bfloat16(v.z - __bfloat162float(h2));
        __nv_bfloat16 l3 = __float2bfloat16(v.w - __bfloat162float(h3));
        __nv_bfloat162 p;
        p.x = h0; p.y = h1; ((__nv_bfloat162*)g_xhi)[2 * i]     = p;
        p.x = h2; p.y = h3; ((__nv_bfloat162*)g_xhi)[2 * i + 1] = p;
        p.x = l0; p.y = l1; ((__nv_bfloat162*)g_xlo)[2 * i]     = p;
        p.x = l2; p.y = l3; ((__nv_bfloat162*)g_xlo)[2 * i + 1] = p;
    } else {
        int w = b - NXB;
        int e = w >> 8;
        int k0 = ((w >> 4) & 15) * 32, nb = (w & 15) * 32;
        int tx = tid & 31, ty = tid >> 5;      // 32 x 8
        const float* Wb = W + (size_t)e * DIM * DIM;
#pragma unroll
        for (int i = 0; i < 4; i++)
            t[ty + i * 8][tx] = Wb[(size_t)(k0 + ty + i * 8) * DIM + nb + tx];
        __syncthreads();
#pragma unroll
        for (int i = 0; i < 4; i++) {
            float v = t[tx][ty + i * 8];       // = W[e][k0+tx][nb+ty+i*8]
            __nv_bfloat16 h = __float2bfloat16(v);
            __nv_bfloat16 l = __float2bfloat16(v - __bfloat162float(h));
            size_t o = (size_t)e * DIM * DIM + (size_t)(nb + ty + i * 8) * DIM + (k0 + tx);
            g_whi[o] = h;
            g_wlo[o] = l;
        }
    }
}

// ---------------- HMMA grouped GEMM (occupancy 2) -----------------------------
__global__ __launch_bounds__(256, 2)
void k_gemm(float* __restrict__ out) {
    extern __shared__ char smem[];
    const int tid = threadIdx.x;
    const int total = g_offsets[NBIN];
    const int row0 = blockIdx.x * BM;
    if (row0 >= total) return;

    const uint32_t sb = smem_u32(smem);
    int* rowid_s = (int*)(smem + SM_ROWID);

    int bin = 0;
#pragma unroll
    for (int k = 1; k < NBIN; k++)
        if (row0 >= g_offsets[k]) bin = k;

    if (tid < BM) rowid_s[tid] = g_perm[row0 + tid];
    __syncthreads();

    // gather tokens for A loads: thread covers rows (tid>>3) + 32*i
    int tokA[4];
#pragma unroll
    for (int i = 0; i < 4; i++) {
        int t = rowid_s[(tid >> 3) + i * 32];
        tokA[i] = t < 0 ? 0 : t;
    }

    const int n0 = blockIdx.y * BN;
    const size_t wrow0 = (size_t)bin * DIM + n0;   // W n-row base

    auto load_chunk = [&](int ch) {
        const int st = ch % NSTAGE;
        const int kt = ch * BKC;
        const uint32_t ab = sb + SM_TILES + st * STAGE_BYTES;
        const uint32_t bb = ab + 16384;
#pragma unroll
        for (int i = 0; i < 4; i++) {
            int s = tid + i * 256;
            int r = s >> 3, c = s & 7;                 // c: 16B chunk in 128B row
            const __nv_bfloat16* src = (c < 4)
                ? g_xhi + ((size_t)tokA[i] * DIM + kt + c * 8)
                : g_xlo + ((size_t)tokA[i] * DIM + kt + (c - 4) * 8);
            cp16(ab + sw128((uint32_t)(r * 128 + c * 16)), src);
        }
#pragma unroll
        for (int i = 0; i < 4; i++) {
            int s = tid + i * 256;
            int r = s >> 3, c = s & 7;
            const __nv_bfloat16* src = (c < 4)
                ? g_whi + ((wrow0 + r) * DIM + kt + c * 8)
                : g_wlo + ((wrow0 + r) * DIM + kt + (c - 4) * 8);
            cp16(bb + sw128((uint32_t)(r * 128 + c * 16)), src);
        }
        cp_commit();
    };

    load_chunk(0);
    load_chunk(1);

    const int lane = tid & 31;
    const int wid = tid >> 5;
    const int wm = (wid & 1) * 64;       // warp M offset (2 warps in M)
    const int wn = (wid >> 1) * 32;      // warp N offset (4 warps in N)
    const int lrow = lane & 15;
    const int lc16 = (lane >> 4) * 16;

    float acc[4][4][4];
#pragma unroll
    for (int i = 0; i < 4; i++)
#pragma unroll
        for (int j = 0; j < 4; j++)
#pragma unroll
            for (int q = 0; q < 4; q++) acc[i][j][q] = 0.f;

#pragma unroll 1
    for (int c = 0; c < NCHUNK; c++) {
        if (c + 1 < NCHUNK) cp_wait1(); else cp_wait0();
        __syncthreads();
        if (c + 2 < NCHUNK) load_chunk(c + 2);

        const uint32_t ab = sb + SM_TILES + (c % NSTAGE) * STAGE_BYTES;
        const uint32_t bb = ab + 16384;

#pragma unroll
        for (int kk = 0; kk < 2; kk++) {        // two k16 steps per 32-chunk
            uint32_t Bh[4][2], Bl[4][2];
#pragma unroll
            for (int bt = 0; bt < 2; bt++) {    // x4 covers two n8 tiles
                uint32_t off = (uint32_t)((wn + bt * 16 + lrow) * 128 + kk * 32 + lc16);
                uint32_t r[4];
                ldsm4(r, bb + sw128(off));
                Bh[2 * bt][0] = r[0]; Bh[2 * bt][1] = r[2];
                Bh[2 * bt + 1][0] = r[1]; Bh[2 * bt + 1][1] = r[3];
                ldsm4(r, bb + sw128(off + 64));
                Bl[2 * bt][0] = r[0]; Bl[2 * bt][1] = r[2];
                Bl[2 * bt + 1][0] = r[1]; Bl[2 * bt + 1][1] = r[3];
            }
#pragma unroll
            for (int mt = 0; mt < 4; mt++) {
                uint32_t Ah[4], Al[4];
                uint32_t off = (uint32_t)((wm + mt * 16 + lrow) * 128 + kk * 32 + lc16);
                ldsm4(Ah, ab + sw128(off));
                ldsm4(Al, ab + sw128(off + 64));
#pragma unroll
                for (int nt = 0; nt < 4; nt++) {
                    mma16816(acc[mt][nt], Ah, Bh[nt]);
                    mma16816(acc[mt][nt], Ah, Bl[nt]);
                    mma16816(acc[mt][nt], Al, Bh[nt]);
                }
            }
        }
        __syncthreads();
    }

    // epilogue: scatter acc to gmem through perm
    const int rq = lane >> 2;
    const int cq = (lane & 3) * 2;
#pragma unroll
    for (int mt = 0; mt < 4; mt++) {
        int rA = wm + mt * 16 + rq;
        int tA = rowid_s[rA];
        int tB = rowid_s[rA + 8];
#pragma unroll
        for (int nt = 0; nt < 4; nt++) {
            int col = n0 + wn + nt * 8 + cq;
            if (tA >= 0)
                *(float2*)(out + (size_t)tA * DIM + col) =
                    make_float2(acc[mt][nt][0], acc[mt][nt][1]);
            if (tB >= 0)
                *(float2*)(out + (size_t)tB * DIM + col) =
                    make_float2(acc[mt][nt][2], acc[mt][nt][3]);
        }
    }
}

// ---------------- launch --------------------------------------------------------
extern "C" void kernel_launch(void* const* d_in, const int* in_sizes, int n_in,
                              void* d_out, int out_size) {
    const float* x = (const float*)d_in[0];   // [8,4096,512] f32
    const float* W = (const float*)d_in[1];   // [8,512,512]  f32
    float* out = (float*)d_out;

    k_prep<<<(PERM_CAP + 255) / 256, 256>>>(x);
    k_scatter<<<NTBLK, 256>>>();
    k_convert<<<NXB + NWB, 256>>>(x, W);

    cudaFuncSetAttribute(k_gemm, cudaFuncAttributeMaxDynamicSharedMemorySize, SM_TOTAL);
    k_gemm<<<dim3(MAX_TILES_M, DIM / BN), 256, SM_TOTAL>>>(out);
}

// round 9
// speedup vs baseline: 2.0902x; 1.0882x over previous
#include <cuda_runtime.h>
#include <cuda_bf16.h>
#include <cstdint>

// ---------------------------------------------------------------------------
// DispatchByVariable: grouped GEMM via mma.sync bf16 split (hi/lo, 3 MMAs)
//   x  : [8,4096,512] f32  (32768 tokens x 512)
//   W  : [8,512,512]  f32  (8 experts)
//   out[t] = x[t] @ W[bin(t)],  bin = sum(x[t,0] > {-1.5..1.5})
// R8 post-mortem: tensor pipe 48.8% — latency-exposed, not rate-capped.
// R9: split-major MMA reorder (dep dist 8), single barrier/chunk, mid-chunk
//     cp.async issue, register-resident gmem pointers & smem offsets.
// ---------------------------------------------------------------------------

#define NTOK 32768
#define DIM  512
#define NBIN 8
#define BM   128
#define BN   128
#define BKC  32
#define NCHUNK (DIM / BKC)                 // 16
#define PERM_CAP (NTOK + NBIN * BM)        // 33792
#define MAX_TILES_M (NTOK / BM + NBIN)     // 264
#define NSTAGE 3
#define NTBLK (NTOK / 256)                 // 128 token blocks

// ---------------- device scratch (no allocs) --------------------------------
__device__ int g_binof[NTOK];
__device__ int g_perm[PERM_CAP];
__device__ int g_hist[NTBLK][NBIN];
__device__ int g_offsets[NBIN + 1];
__device__ __align__(256) __nv_bfloat16 g_xhi[NTOK * DIM];       // 32 MB
__device__ __align__(256) __nv_bfloat16 g_xlo[NTOK * DIM];       // 32 MB
__device__ __align__(256) __nv_bfloat16 g_whi[NBIN * DIM * DIM]; // 4 MB, K-major [e][n][k]
__device__ __align__(256) __nv_bfloat16 g_wlo[NBIN * DIM * DIM];

// ---------------- smem layout for GEMM (dynamic) -----------------------------
#define SM_ROWID 0            // 128 ints
#define SM_TILES 1024
#define STAGE_BYTES 32768     // A 16KB + B 16KB
#define SM_TOTAL (SM_TILES + NSTAGE * STAGE_BYTES)   // 99328 -> 2 CTAs/SM

// ---------------- PTX helpers ------------------------------------------------
__device__ __forceinline__ uint32_t smem_u32(const void* p) {
    uint32_t a;
    asm("{ .reg .u64 t; cvta.to.shared.u64 t, %1; cvt.u32.u64 %0, t; }"
        : "=r"(a) : "l"(p));
    return a;
}
__device__ __forceinline__ uint32_t sw128(uint32_t b) { return b ^ ((b >> 3) & 0x70); }

__device__ __forceinline__ void cp16(uint32_t d, const void* s) {
    asm volatile("cp.async.cg.shared.global [%0], [%1], 16;" :: "r"(d), "l"(s));
}
__device__ __forceinline__ void cp_commit() { asm volatile("cp.async.commit_group;"); }
__device__ __forceinline__ void cp_wait1()  { asm volatile("cp.async.wait_group 1;"); }
__device__ __forceinline__ void cp_wait0()  { asm volatile("cp.async.wait_group 0;"); }

__device__ __forceinline__ void ldsm4(uint32_t* r, uint32_t a) {
    asm volatile("ldmatrix.sync.aligned.m8n8.x4.shared.b16 {%0,%1,%2,%3}, [%4];"
                 : "=r"(r[0]), "=r"(r[1]), "=r"(r[2]), "=r"(r[3]) : "r"(a));
}
__device__ __forceinline__ void mma16816(float* c, const uint32_t* a,
                                         const uint32_t* b0) {
    asm volatile(
        "mma.sync.aligned.m16n8k16.row.col.f32.bf16.bf16.f32 "
        "{%0,%1,%2,%3},{%4,%5,%6,%7},{%8,%9},{%0,%1,%2,%3};"
        : "+f"(c[0]), "+f"(c[1]), "+f"(c[2]), "+f"(c[3])
        : "r"(a[0]), "r"(a[1]), "r"(a[2]), "r"(a[3]), "r"(b0[0]), "r"(b0[1]));
}

// ---------------- prep kernel 1: perm init + bucketize (smem hist) -----------
__global__ void k_prep(const float* __restrict__ x) {
    __shared__ int hist[NBIN];
    const int b = blockIdx.x, tid = threadIdx.x;
    const int i = b * 256 + tid;
    if (i < PERM_CAP) g_perm[i] = -1;
    if (b < NTBLK) {
        if (tid < NBIN) hist[tid] = 0;
        __syncthreads();
        float y = x[(size_t)i * DIM];
        int bin = 0;
        bin += (y > -1.5f); bin += (y > -1.0f); bin += (y > -0.5f); bin += (y > 0.0f);
        bin += (y >  0.5f); bin += (y >  1.0f); bin += (y >  1.5f);
        g_binof[i] = bin;
        atomicAdd(&hist[bin], 1);          // smem only
        __syncthreads();
        if (tid < NBIN) g_hist[b][tid] = hist[tid];
    }
}

// ---------------- prep kernel 2: deterministic scatter (no global atomics) ---
__global__ void k_scatter() {
    __shared__ int base[NBIN], totals[NBIN], offs[NBIN], cnt[NBIN];
    const int b = blockIdx.x, tid = threadIdx.x;
    if (tid < NBIN) {
        int pre = 0, tot = 0;
        for (int q = 0; q < NTBLK; q++) {
            int h = g_hist[q][tid];
            if (q < b) pre += h;
            tot += h;
        }
        base[tid] = pre; totals[tid] = tot; cnt[tid] = 0;
    }
    __syncthreads();
    if (tid == 0) {
        int off = 0;
        for (int k = 0; k < NBIN; k++) {
            offs[k] = off;
            if (b == 0) g_offsets[k] = off;
            off += ((totals[k] + BM - 1) / BM) * BM;
        }
        if (b == 0) g_offsets[NBIN] = off;
    }
    __syncthreads();
    const int t = b * 256 + tid;
    const int bin = g_binof[t];
    const int r = atomicAdd(&cnt[bin], 1);     // smem only
    g_perm[offs[bin] + base[bin] + r] = t;
}

// ---------------- fused convert: x -> hi/lo bf16, W -> transposed hi/lo ------
#define NXB (NTOK * DIM / 4 / 256)    // 16384 blocks for x
#define NWB (16 * 16 * NBIN)          // 2048 blocks for W
__global__ void k_convert(const float* __restrict__ x, const float* __restrict__ W) {
    __shared__ float t[32][33];
    const int b = blockIdx.x, tid = threadIdx.x;
    if (b < NXB) {
        int i = b * 256 + tid;                 // float4 index
        float4 v = ((const float4*)x)[i];
        __nv_bfloat16 h0 = __float2bfloat16(v.x), h1 = __float2bfloat16(v.y);
        __nv_bfloat16 h2 = __float2bfloat16(v.z), h3 = __float2bfloat16(v.w);
        __nv_bfloat16 l0 = __float2bfloat16(v.x - __bfloat162float(h0));
        __nv_bfloat16 l1 = __float2bfloat16(v.y - __bfloat162float(h1));
        __nv_bfloat16 l2 = __float2bfloat16(v.z - __bfloat162float(h2));
        __nv_bfloat16 l3 = __float2bfloat16(v.w - __bfloat162float(h3));
        __nv_bfloat162 p;
        p.x = h0; p.y = h1; ((__nv_bfloat162*)g_xhi)[2 * i]     = p;
        p.x = h2; p.y = h3; ((__nv_bfloat162*)g_xhi)[2 * i + 1] = p;
        p.x = l0; p.y = l1; ((__nv_bfloat162*)g_xlo)[2 * i]     = p;
        p.x = l2; p.y = l3; ((__nv_bfloat162*)g_xlo)[2 * i + 1] = p;
    } else {
        int w = b - NXB;
        int e = w >> 8;
        int k0 = ((w >> 4) & 15) * 32, nb = (w & 15) * 32;
        int tx = tid & 31, ty = tid >> 5;      // 32 x 8
        const float* Wb = W + (size_t)e * DIM * DIM;
#pragma unroll
        for (int i = 0; i < 4; i++)
            t[ty + i * 8][tx] = Wb[(size_t)(k0 + ty + i * 8) * DIM + nb + tx];
        __syncthreads();
#pragma unroll
        for (int i = 0; i < 4; i++) {
            float v = t[tx][ty + i * 8];       // = W[e][k0+tx][nb+ty+i*8]
            __nv_bfloat16 h = __float2bfloat16(v);
            __nv_bfloat16 l = __float2bfloat16(v - __bfloat162float(h));
            size_t o = (size_t)e * DIM * DIM + (size_t)(nb + ty + i * 8) * DIM + (k0 + tx);
            g_whi[o] = h;
            g_wlo[o] = l;
        }
    }
}

// ---------------- HMMA grouped GEMM (occupancy 2, latency-optimized) ----------
__global__ __launch_bounds__(256, 2)
void k_gemm(float* __restrict__ out) {
    extern __shared__ char smem[];
    const int tid = threadIdx.x;
    const int total = g_offsets[NBIN];
    const int row0 = blockIdx.x * BM;
    if (row0 >= total) return;

    const uint32_t sb = smem_u32(smem);
    int* rowid_s = (int*)(smem + SM_ROWID);

    int bin = 0;
#pragma unroll
    for (int k = 1; k < NBIN; k++)
        if (row0 >= g_offsets[k]) bin = k;

    if (tid < BM) rowid_s[tid] = g_perm[row0 + tid];
    __syncthreads();

    const int n0 = blockIdx.y * BN;
    const size_t wrow0 = (size_t)bin * DIM + n0;   // W n-row base

    // --- register-resident load plumbing (advance by 64B per chunk) ---------
    const int cc = tid & 7;                    // 16B chunk within 128B smem row
    const ptrdiff_t dxlo = (const char*)g_xlo - (const char*)g_xhi;
    const ptrdiff_t dwlo = (const char*)g_wlo - (const char*)g_whi;
    const ptrdiff_t hl_off = (cc < 4) ? (ptrdiff_t)cc * 16
                                      : (ptrdiff_t)(cc - 4) * 16;
    const char* srcA[4];
    const char* srcB[4];
    uint32_t dst[4];
#pragma unroll
    for (int i = 0; i < 4; i++) {
        int r = (tid >> 3) + 32 * i;
        int t = rowid_s[r];
        if (t < 0) t = 0;
        dst[i] = sw128((uint32_t)(r * 128 + cc * 16));
        srcA[i] = (const char*)g_xhi + (size_t)t * DIM * 2 + hl_off
                  + (cc < 4 ? 0 : dxlo);
        srcB[i] = (const char*)g_whi + (wrow0 + r) * DIM * 2 + hl_off
                  + (cc < 4 ? 0 : dwlo);
    }

    auto load_chunk = [&](int st) {
        const uint32_t ab = sb + SM_TILES + st * STAGE_BYTES;
        const uint32_t bb = ab + 16384;
#pragma unroll
        for (int i = 0; i < 4; i++) cp16(ab + dst[i], srcA[i]);
#pragma unroll
        for (int i = 0; i < 4; i++) cp16(bb + dst[i], srcB[i]);
#pragma unroll
        for (int i = 0; i < 4; i++) { srcA[i] += 64; srcB[i] += 64; }
        cp_commit();
    };

    load_chunk(0);
    load_chunk(1);

    const int lane = tid & 31;
    const int wid = tid >> 5;
    const int wm = (wid & 1) * 64;       // warp M offset (2 warps in M)
    const int wn = (wid >> 1) * 32;      // warp N offset (4 warps in N)
    const int lrow = lane & 15;
    const int lc16 = (lane >> 4) * 16;

    float acc[4][4][4];
#pragma unroll
    for (int i = 0; i < 4; i++)
#pragma unroll
        for (int j = 0; j < 4; j++)
#pragma unroll
            for (int q = 0; q < 4; q++) acc[i][j][q] = 0.f;

    // one kk-step (K=16): split-major MMA order, dep distance 8 per chain
    auto compute = [&](uint32_t ab, uint32_t bb, int kk) {
        uint32_t Bh[4][2], Bl[4][2];
#pragma unroll
        for (int bt = 0; bt < 2; bt++) {
            uint32_t off = (uint32_t)((wn + bt * 16 + lrow) * 128 + kk * 32 + lc16);
            uint32_t r[4];
            ldsm4(r, bb + sw128(off));
            Bh[2 * bt][0] = r[0]; Bh[2 * bt][1] = r[2];
            Bh[2 * bt + 1][0] = r[1]; Bh[2 * bt + 1][1] = r[3];
            ldsm4(r, bb + sw128(off + 64));
            Bl[2 * bt][0] = r[0]; Bl[2 * bt][1] = r[2];
            Bl[2 * bt + 1][0] = r[1]; Bl[2 * bt + 1][1] = r[3];
        }
#pragma unroll
        for (int mp = 0; mp < 2; mp++) {       // m-pairs: 2 rows of 16
            uint32_t Ah[2][4], Al[2][4];
#pragma unroll
            for (int m = 0; m < 2; m++) {
                uint32_t off = (uint32_t)((wm + (2 * mp + m) * 16 + lrow) * 128
                                          + kk * 32 + lc16);
                ldsm4(Ah[m], ab + sw128(off));
                ldsm4(Al[m], ab + sw128(off + 64));
            }
            // split-major: 8 independent MMAs per group
#pragma unroll
            for (int m = 0; m < 2; m++)
#pragma unroll
                for (int nt = 0; nt < 4; nt++)
                    mma16816(acc[2 * mp + m][nt], Ah[m], Bh[nt]);
#pragma unroll
            for (int m = 0; m < 2; m++)
#pragma unroll
                for (int nt = 0; nt < 4; nt++)
                    mma16816(acc[2 * mp + m][nt], Ah[m], Bl[nt]);
#pragma unroll
            for (int m = 0; m < 2; m++)
#pragma unroll
                for (int nt = 0; nt < 4; nt++)
                    mma16816(acc[2 * mp + m][nt], Al[m], Bh[nt]);
        }
    };

#pragma unroll 1
    for (int c = 0; c < NCHUNK; c++) {
        if (c + 1 < NCHUNK) cp_wait1(); else cp_wait0();
        __syncthreads();                       // single barrier per chunk
        const uint32_t ab = sb + SM_TILES + (c % NSTAGE) * STAGE_BYTES;
        const uint32_t bb = ab + 16384;
        compute(ab, bb, 0);
        if (c + 2 < NCHUNK) load_chunk((c + 2) % NSTAGE);  // overlap with MMAs
        compute(ab, bb, 1);
    }

    // epilogue: scatter acc to gmem through perm
    const int rq = lane >> 2;
    const int cq = (lane & 3) * 2;
#pragma unroll
    for (int mt = 0; mt < 4; mt++) {
        int rA = wm + mt * 16 + rq;
        int tA = rowid_s[rA];
        int tB = rowid_s[rA + 8];
#pragma unroll
        for (int nt = 0; nt < 4; nt++) {
            int col = n0 + wn + nt * 8 + cq;
            if (tA >= 0)
                *(float2*)(out + (size_t)tA * DIM + col) =
                    make_float2(acc[mt][nt][0], acc[mt][nt][1]);
            if (tB >= 0)
                *(float2*)(out + (size_t)tB * DIM + col) =
                    make_float2(acc[mt][nt][2], acc[mt][nt][3]);
        }
    }
}

// ---------------- launch --------------------------------------------------------
extern "C" void kernel_launch(void* const* d_in, const int* in_sizes, int n_in,
                              void* d_out, int out_size) {
    const float* x = (const float*)d_in[0];   // [8,4096,512] f32
    const float* W = (const float*)d_in[1];   // [8,512,512]  f32
    float* out = (float*)d_out;

    k_prep<<<(PERM_CAP + 255) / 256, 256>>>(x);
    k_scatter<<<NTBLK, 256>>>();
    k_convert<<<NXB + NWB, 256>>>(x, W);

    cudaFuncSetAttribute(k_gemm, cudaFuncAttributeMaxDynamicSharedMemorySize, SM_TOTAL);
    k_gemm<<<dim3(MAX_TILES_M, DIM / BN), 256, SM_TOTAL>>>(out);
}

// round 11
// speedup vs baseline: 2.1983x; 1.0517x over previous
#include <cuda_runtime.h>
#include <cuda_bf16.h>
#include <cstdint>

// ---------------------------------------------------------------------------
// DispatchByVariable: grouped GEMM via mma.sync bf16 split (hi/lo, 3 MMAs)
//   x  : [8,4096,512] f32  (32768 tokens x 512)
//   W  : [8,512,512]  f32  (8 experts)
//   out[t] = x[t] @ W[bin(t)],  bin = sum(x[t,0] > {-1.5..1.5})
// R10 post-mortem: sw128(b)+delta is WRONG (XOR field carries into bit 7,
//   overran the smem allocation at the last stage). Correct: sw128(b)^delta
//   (valid since pre-swizzle bits 5,6 of base are 0). Also LOQ unit fix.
// R11: R10 pipeline with XOR-corrected swizzle deltas.
// ---------------------------------------------------------------------------

#define NTOK 32768
#define DIM  512
#define NBIN 8
#define BM   128
#define BN   128
#define BKC  32
#define NCHUNK (DIM / BKC)                 // 16
#define PERM_CAP (NTOK + NBIN * BM)        // 33792
#define MAX_TILES_M (NTOK / BM + NBIN)     // 264
#define NSTAGE 3
#define NTBLK (NTOK / 256)                 // 128 token blocks
#define XHALF ((uint32_t)NTOK * DIM * 2)   // byte offset of x_lo half (32MB)
#define WHALF ((uint32_t)NBIN * DIM * DIM * 2)  // byte offset of w_lo half (4MB)

// ---------------- device scratch (no allocs) --------------------------------
__device__ int g_binof[NTOK];
__device__ int g_perm[PERM_CAP];
__device__ int g_hist[NTBLK][NBIN];
__device__ int g_offsets[NBIN + 1];
// merged hi|lo halves: [0, XHALF) = hi bytes, [XHALF, 2*XHALF) = lo bytes
__device__ __align__(256) __nv_bfloat16 g_x2[2u * NTOK * DIM];        // 64 MB
__device__ __align__(256) __nv_bfloat16 g_w2[2u * NBIN * DIM * DIM];  // 8 MB, K-major [e][n][k]

// ---------------- smem layout for GEMM (dynamic) -----------------------------
#define SM_ROWID 0            // 128 ints
#define SM_TILES 1024
#define STAGE_BYTES 32768     // A 16KB + B 16KB
#define SM_TOTAL (SM_TILES + NSTAGE * STAGE_BYTES)   // 99328 -> 2 CTAs/SM

// ---------------- PTX helpers ------------------------------------------------
__device__ __forceinline__ uint32_t smem_u32(const void* p) {
    uint32_t a;
    asm("{ .reg .u64 t; cvta.to.shared.u64 t, %1; cvt.u32.u64 %0, t; }"
        : "=r"(a) : "l"(p));
    return a;
}
__device__ __forceinline__ uint32_t sw128(uint32_t b) { return b ^ ((b >> 3) & 0x70); }

__device__ __forceinline__ void cp16(uint32_t d, const void* s) {
    asm volatile("cp.async.cg.shared.global [%0], [%1], 16;" :: "r"(d), "l"(s));
}
__device__ __forceinline__ void cp_commit() { asm volatile("cp.async.commit_group;"); }
__device__ __forceinline__ void cp_wait1()  { asm volatile("cp.async.wait_group 1;"); }
__device__ __forceinline__ void cp_wait0()  { asm volatile("cp.async.wait_group 0;"); }

__device__ __forceinline__ void ldsm4(uint32_t* r, uint32_t a) {
    asm volatile("ldmatrix.sync.aligned.m8n8.x4.shared.b16 {%0,%1,%2,%3}, [%4];"
                 : "=r"(r[0]), "=r"(r[1]), "=r"(r[2]), "=r"(r[3]) : "r"(a));
}
__device__ __forceinline__ void mma16816(float* c, const uint32_t* a,
                                         const uint32_t* b0) {
    asm volatile(
        "mma.sync.aligned.m16n8k16.row.col.f32.bf16.bf16.f32 "
        "{%0,%1,%2,%3},{%4,%5,%6,%7},{%8,%9},{%0,%1,%2,%3};"
        : "+f"(c[0]), "+f"(c[1]), "+f"(c[2]), "+f"(c[3])
        : "r"(a[0]), "r"(a[1]), "r"(a[2]), "r"(a[3]), "r"(b0[0]), "r"(b0[1]));
}
// B ldsm: x4 covers two n8 tiles (2bt, 2bt+1)
__device__ __forceinline__ void ldB(uint32_t addr, uint32_t Bf[4][2], int bt) {
    uint32_t r[4];
    ldsm4(r, addr);
    Bf[2 * bt][0] = r[0]; Bf[2 * bt][1] = r[2];
    Bf[2 * bt + 1][0] = r[1]; Bf[2 * bt + 1][1] = r[3];
}
// 8 independent MMAs: m-pair (m0, m0+1) x 4 n-tiles
__device__ __forceinline__ void mma_grp(float acc[4][4][4], int m0,
                                        const uint32_t A[2][4],
                                        const uint32_t B[4][2]) {
#pragma unroll
    for (int m = 0; m < 2; m++)
#pragma unroll
        for (int nt = 0; nt < 4; nt++)
            mma16816(acc[m0 + m][nt], A[m], B[nt]);
}

// ---------------- prep kernel 1: perm init + bucketize (smem hist) -----------
__global__ void k_prep(const float* __restrict__ x) {
    __shared__ int hist[NBIN];
    const int b = blockIdx.x, tid = threadIdx.x;
    const int i = b * 256 + tid;
    if (i < PERM_CAP) g_perm[i] = -1;
    if (b < NTBLK) {
        if (tid < NBIN) hist[tid] = 0;
        __syncthreads();
        float y = x[(size_t)i * DIM];
        int bin = 0;
        bin += (y > -1.5f); bin += (y > -1.0f); bin += (y > -0.5f); bin += (y > 0.0f);
        bin += (y >  0.5f); bin += (y >  1.0f); bin += (y >  1.5f);
        g_binof[i] = bin;
        atomicAdd(&hist[bin], 1);          // smem only
        __syncthreads();
        if (tid < NBIN) g_hist[b][tid] = hist[tid];
    }
}

// ---------------- prep kernel 2: deterministic scatter (no global atomics) ---
__global__ void k_scatter() {
    __shared__ int base[NBIN], totals[NBIN], offs[NBIN], cnt[NBIN];
    const int b = blockIdx.x, tid = threadIdx.x;
    if (tid < NBIN) {
        int pre = 0, tot = 0;
        for (int q = 0; q < NTBLK; q++) {
            int h = g_hist[q][tid];
            if (q < b) pre += h;
            tot += h;
        }
        base[tid] = pre; totals[tid] = tot; cnt[tid] = 0;
    }
    __syncthreads();
    if (tid == 0) {
        int off = 0;
        for (int k = 0; k < NBIN; k++) {
            offs[k] = off;
            if (b == 0) g_offsets[k] = off;
            off += ((totals[k] + BM - 1) / BM) * BM;
        }
        if (b == 0) g_offsets[NBIN] = off;
    }
    __syncthreads();
    const int t = b * 256 + tid;
    const int bin = g_binof[t];
    const int r = atomicAdd(&cnt[bin], 1);     // smem only
    g_perm[offs[bin] + base[bin] + r] = t;
}

// ---------------- fused convert: x -> hi/lo bf16, W -> transposed hi/lo ------
#define NXB (NTOK * DIM / 4 / 256)    // 16384 blocks for x
#define NWB (16 * 16 * NBIN)          // 2048 blocks for W
__global__ void k_convert(const float* __restrict__ x, const float* __restrict__ W) {
    __shared__ float t[32][33];
    const int b = blockIdx.x, tid = threadIdx.x;
    if (b < NXB) {
        int i = b * 256 + tid;                 // float4 index
        const uint32_t LOQ = XHALF / 4;        // lo half start, bf16x2 (4B) units
        float4 v = ((const float4*)x)[i];
        __nv_bfloat16 h0 = __float2bfloat16(v.x), h1 = __float2bfloat16(v.y);
        __nv_bfloat16 h2 = __float2bfloat16(v.z), h3 = __float2bfloat16(v.w);
        __nv_bfloat16 l0 = __float2bfloat16(v.x - __bfloat162float(h0));
        __nv_bfloat16 l1 = __float2bfloat16(v.y - __bfloat162float(h1));
        __nv_bfloat16 l2 = __float2bfloat16(v.z - __bfloat162float(h2));
        __nv_bfloat16 l3 = __float2bfloat16(v.w - __bfloat162float(h3));
        __nv_bfloat162 p;
        p.x = h0; p.y = h1; ((__nv_bfloat162*)g_x2)[2 * i]           = p;
        p.x = h2; p.y = h3; ((__nv_bfloat162*)g_x2)[2 * i + 1]       = p;
        p.x = l0; p.y = l1; ((__nv_bfloat162*)g_x2)[LOQ + 2 * i]     = p;
        p.x = l2; p.y = l3; ((__nv_bfloat162*)g_x2)[LOQ + 2 * i + 1] = p;
    } else {
        int w = b - NXB;
        int e = w >> 8;
        int k0 = ((w >> 4) & 15) * 32, nb = (w & 15) * 32;
        int tx = tid & 31, ty = tid >> 5;      // 32 x 8
        const float* Wb = W + (size_t)e * DIM * DIM;
#pragma unroll
        for (int i = 0; i < 4; i++)
            t[ty + i * 8][tx] = Wb[(size_t)(k0 + ty + i * 8) * DIM + nb + tx];
        __syncthreads();
        const uint32_t LOW = WHALF / 2;        // lo half start, bf16 elements
#pragma unroll
        for (int i = 0; i < 4; i++) {
            float v = t[tx][ty + i * 8];       // = W[e][k0+tx][nb+ty+i*8]
            __nv_bfloat16 h = __float2bfloat16(v);
            __nv_bfloat16 l = __float2bfloat16(v - __bfloat162float(h));
            size_t o = (size_t)e * DIM * DIM + (size_t)(nb + ty + i * 8) * DIM + (k0 + tx);
            g_w2[o] = h;
            g_w2[LOW + o] = l;
        }
    }
}

// ---------------- HMMA grouped GEMM (hand-pipelined, XOR-swizzle deltas) -----
__global__ __launch_bounds__(256, 2)
void k_gemm(float* __restrict__ out) {
    extern __shared__ char smem[];
    const int tid = threadIdx.x;
    const int total = g_offsets[NBIN];
    const int row0 = blockIdx.x * BM;
    if (row0 >= total) return;

    const uint32_t sb = smem_u32(smem);
    int* rowid_s = (int*)(smem + SM_ROWID);

    int bin = 0;
#pragma unroll
    for (int k = 1; k < NBIN; k++)
        if (row0 >= g_offsets[k]) bin = k;

    if (tid < BM) rowid_s[tid] = g_perm[row0 + tid];
    __syncthreads();

    const int n0 = blockIdx.y * BN;
    const uint32_t wrow0 = (uint32_t)bin * DIM + n0;   // W n-row base

    // --- u32 byte-offset plumbing (one base pointer per array) --------------
    const int cc = tid & 7;                    // 16B chunk within 128B smem row
    const uint32_t hl16 = (uint32_t)(cc & 3) * 16;
    const uint32_t dst0 = sw128((uint32_t)((tid >> 3) * 128) + (uint32_t)cc * 16);
    uint32_t offA[4];
#pragma unroll
    for (int i = 0; i < 4; i++) {
        int t = rowid_s[(tid >> 3) + 32 * i];
        if (t < 0) t = 0;
        offA[i] = (cc < 4 ? 0u : XHALF) + (uint32_t)t * 1024u + hl16;
    }
    uint32_t offB = (cc < 4 ? 0u : WHALF)
                  + (wrow0 + (uint32_t)(tid >> 3)) * 1024u + hl16;
    const char* const baseX = (const char*)g_x2;
    const char* const baseW = (const char*)g_w2;

    const int lane = tid & 31;
    const int wid = tid >> 5;
    const int wm = (wid & 1) * 64;       // warp M offset (2 warps in M)
    const int wn = (wid >> 1) * 32;      // warp N offset (4 warps in N)
    const int lrow = lane & 15;
    const int lc16 = (lane >> 4) * 16;

    // ldsm base offsets. kk (+32) / lo (+64) variants via XOR: the pre-swizzle
    // base has bits 5,6 = 0 (lc16 <= 16), so base+d == base^d and
    // sw128(base^d) == sw128(base)^d for d in {32, 64, 96}.
    uint32_t aOff[4], bOff[2];
#pragma unroll
    for (int mt = 0; mt < 4; mt++)
        aOff[mt] = sw128((uint32_t)((wm + mt * 16 + lrow) * 128 + lc16));
#pragma unroll
    for (int bt = 0; bt < 2; bt++)
        bOff[bt] = sw128((uint32_t)((wn + bt * 16 + lrow) * 128 + lc16));

    auto loadA = [&](uint32_t ab) {
#pragma unroll
        for (int i = 0; i < 4; i++) cp16(ab + dst0 + i * 4096u, baseX + offA[i]);
#pragma unroll
        for (int i = 0; i < 4; i++) offA[i] += 64u;
    };
    auto loadB = [&](uint32_t bb) {
#pragma unroll
        for (int i = 0; i < 4; i++) cp16(bb + dst0 + i * 4096u, baseW + offB + i * 32768u);
        offB += 64u;
    };

    {   // prologue: chunks 0 and 1
        uint32_t ab = sb + SM_TILES;
        loadA(ab); loadB(ab + 16384); cp_commit();
        ab += STAGE_BYTES;
        loadA(ab); loadB(ab + 16384); cp_commit();
    }

    float acc[4][4][4];
#pragma unroll
    for (int i = 0; i < 4; i++)
#pragma unroll
        for (int j = 0; j < 4; j++)
#pragma unroll
            for (int q = 0; q < 4; q++) acc[i][j][q] = 0.f;

    uint32_t Bh[4][2], Bl[4][2];
    uint32_t A0h[2][4], A0l[2][4], A1h[2][4], A1l[2][4];

#pragma unroll 1
    for (int c = 0; c < NCHUNK; c++) {
        if (c + 1 < NCHUNK) cp_wait1(); else cp_wait0();
        __syncthreads();                       // single barrier per chunk
        const uint32_t ab = sb + SM_TILES + (c % NSTAGE) * STAGE_BYTES;
        const uint32_t bb = ab + 16384;
        const bool pf = (c + 2 < NCHUNK);
        const uint32_t nab = sb + SM_TILES + ((c + 2) % NSTAGE) * STAGE_BYTES;

        // ---------------- kk = 0 (delta 0 / lo ^64) ----------------
        ldB(bb + bOff[0],         Bh, 0); ldB(bb + (bOff[0] ^ 64u), Bl, 0);
        ldB(bb + bOff[1],         Bh, 1); ldB(bb + (bOff[1] ^ 64u), Bl, 1);
        ldsm4(A0h[0], ab + aOff[0]); ldsm4(A0l[0], ab + (aOff[0] ^ 64u));
        ldsm4(A0h[1], ab + aOff[1]); ldsm4(A0l[1], ab + (aOff[1] ^ 64u));
        mma_grp(acc, 0, A0h, Bh);                    // 8 MMAs
        ldsm4(A1h[0], ab + aOff[2]); ldsm4(A1l[0], ab + (aOff[2] ^ 64u));
        ldsm4(A1h[1], ab + aOff[3]); ldsm4(A1l[1], ab + (aOff[3] ^ 64u));
        mma_grp(acc, 0, A0h, Bl);
        if (pf) loadA(nab);                          // 4 cp.async amid MMAs
        mma_grp(acc, 0, A0l, Bh);
        mma_grp(acc, 2, A1h, Bh);
        if (pf) { loadB(nab + 16384); cp_commit(); } // 4 cp.async + commit
        mma_grp(acc, 2, A1h, Bl);
        mma_grp(acc, 2, A1l, Bh);

        // ---------------- kk = 1 (delta ^32 / lo ^96) ----------------
        ldB(bb + (bOff[0] ^ 32u), Bh, 0); ldB(bb + (bOff[0] ^ 96u), Bl, 0);
        ldB(bb + (bOff[1] ^ 32u), Bh, 1); ldB(bb + (bOff[1] ^ 96u), Bl, 1);
        ldsm4(A0h[0], ab + (aOff[0] ^ 32u)); ldsm4(A0l[0], ab + (aOff[0] ^ 96u));
        ldsm4(A0h[1], ab + (aOff[1] ^ 32u)); ldsm4(A0l[1], ab + (aOff[1] ^ 96u));
        mma_grp(acc, 0, A0h, Bh);
        ldsm4(A1h[0], ab + (aOff[2] ^ 32u)); ldsm4(A1l[0], ab + (aOff[2] ^ 96u));
        ldsm4(A1h[1], ab + (aOff[3] ^ 32u)); ldsm4(A1l[1], ab + (aOff[3] ^ 96u));
        mma_grp(acc, 0, A0h, Bl);
        mma_grp(acc, 0, A0l, Bh);
        mma_grp(acc, 2, A1h, Bh);
        mma_grp(acc, 2, A1h, Bl);
        mma_grp(acc, 2, A1l, Bh);
    }

    // epilogue: scatter acc to gmem through perm
    const int rq = lane >> 2;
    const int cq = (lane & 3) * 2;
#pragma unroll
    for (int mt = 0; mt < 4; mt++) {
        int rA = wm + mt * 16 + rq;
        int tA = rowid_s[rA];
        int tB = rowid_s[rA + 8];
#pragma unroll
        for (int nt = 0; nt < 4; nt++) {
            int col = n0 + wn + nt * 8 + cq;
            if (tA >= 0)
                *(float2*)(out + (size_t)tA * DIM + col) =
                    make_float2(acc[mt][nt][0], acc[mt][nt][1]);
            if (tB >= 0)
                *(float2*)(out + (size_t)tB * DIM + col) =
                    make_float2(acc[mt][nt][2], acc[mt][nt][3]);
        }
    }
}

// ---------------- launch --------------------------------------------------------
extern "C" void kernel_launch(void* const* d_in, const int* in_sizes, int n_in,
                              void* d_out, int out_size) {
    const float* x = (const float*)d_in[0];   // [8,4096,512] f32
    const float* W = (const float*)d_in[1];   // [8,512,512]  f32
    float* out = (float*)d_out;

    k_prep<<<(PERM_CAP + 255) / 256, 256>>>(x);
    k_scatter<<<NTBLK, 256>>>();
    k_convert<<<NXB + NWB, 256>>>(x, W);

    cudaFuncSetAttribute(k_gemm, cudaFuncAttributeMaxDynamicSharedMemorySize, SM_TOTAL);
    k_gemm<<<dim3(MAX_TILES_M, DIM / BN), 256, SM_TOTAL>>>(out);
}